// round 15
// baseline (speedup 1.0000x reference)
#include <cuda_runtime.h>
#include <cstddef>

// Problem dims
#define T_STEPS 16
#define B_DIM   64
#define S_DIM   512
#define H_DIM   2048
#define A_DIM   32
#define MROWS   (T_STEPS * B_DIM)          // 1024 (tb rows)
#define NELEM   ((size_t)MROWS * H_DIM)    // 2,097,152
#define MBIG    (T_STEPS * MROWS)          // 16384
#define KWORDS  (H_DIM / 32)               // 64 bit-words per S1 row
#define PSTRIDE ((size_t)MBIG * H_DIM)     // one slice-partial plane
#define ENTCAP  520                        // per-(tb,slice) entries (u64)
#define SMSTR   68                         // 64 + 4 pad floats per k-row (16B-aligned rows)
#define ZOFF    (512u * SMSTR * 4u)        // byte offset of the zero pad row

// Output layout: concat of (value, action, m1, m2, m_act, m_crit), fp32
#define OFF_VALUE  0
#define OFF_ACTION 1024
#define OFF_M1     33792
#define OFF_M2     2130944
#define OFF_MACT   4228096
#define OFF_MCRIT  4260864

// Scratch (device globals: allocation-free per harness rules)
__device__ float    g_cur1[MROWS * H_DIM];                  // 8 MB
__device__ float    g_W2T[(size_t)H_DIM * H_DIM];           // 16 MB: W2 transposed [k][n]
__device__ unsigned g_S1bits[(size_t)MBIG * KWORDS];        // 4 MB spike bits
__device__ unsigned long long g_ent[(size_t)MROWS * 4 * ENTCAP]; // 17 MB union lists
__device__ unsigned g_cnt[MROWS * 4];                       // padded union counts
__device__ float    g_P[(size_t)4 * MBIG * H_DIM];          // 512 MB slice partials
__device__ float    g_S2[MROWS * H_DIM];                    // 8 MB

// ---------------------------------------------------------------------------
// Packed f32x2 helpers
// ---------------------------------------------------------------------------
__device__ __forceinline__ unsigned long long pack2(float x, float y) {
    unsigned long long r;
    asm("mov.b64 %0, {%1, %2};" : "=l"(r) : "f"(x), "f"(y));
    return r;
}
__device__ __forceinline__ void fma2(unsigned long long& acc,
                                     unsigned long long a,
                                     unsigned long long b) {
    asm("fma.rn.f32x2 %0, %1, %2, %0;" : "+l"(acc) : "l"(a), "l"(b));
}
__device__ __forceinline__ float2 unpack2(unsigned long long v) {
    float2 f;
    asm("mov.b64 {%0, %1}, %2;" : "=f"(f.x), "=f"(f.y) : "l"(v));
    return f;
}

// One entry: 16 predicated packed adds, each gated by ONE LOP3-with-predicate
// (immediate bit mask, LUT 0xc0 = a&b; c operand unused). Skip / +0.0-pad
// adds are bit-neutral (acc never -0) — proven rounds 8-14.
__device__ __forceinline__ void entry_adds(unsigned long long* acc,
                                           unsigned mask,
                                           unsigned long long w) {
    asm("{\n\t"
        ".reg .pred p, q;\n\t"
        ".reg .b32 t;\n\t"
        "setp.ne.b32 q, %16, %16;\n\t"                       // q = false
        "lop3.or.b32 t|p, %16, 1, %16, 0xc0, q;\n\t"
        "@p add.rn.f32x2 %0, %0, %17;\n\t"
        "lop3.or.b32 t|p, %16, 2, %16, 0xc0, q;\n\t"
        "@p add.rn.f32x2 %1, %1, %17;\n\t"
        "lop3.or.b32 t|p, %16, 4, %16, 0xc0, q;\n\t"
        "@p add.rn.f32x2 %2, %2, %17;\n\t"
        "lop3.or.b32 t|p, %16, 8, %16, 0xc0, q;\n\t"
        "@p add.rn.f32x2 %3, %3, %17;\n\t"
        "lop3.or.b32 t|p, %16, 16, %16, 0xc0, q;\n\t"
        "@p add.rn.f32x2 %4, %4, %17;\n\t"
        "lop3.or.b32 t|p, %16, 32, %16, 0xc0, q;\n\t"
        "@p add.rn.f32x2 %5, %5, %17;\n\t"
        "lop3.or.b32 t|p, %16, 64, %16, 0xc0, q;\n\t"
        "@p add.rn.f32x2 %6, %6, %17;\n\t"
        "lop3.or.b32 t|p, %16, 128, %16, 0xc0, q;\n\t"
        "@p add.rn.f32x2 %7, %7, %17;\n\t"
        "lop3.or.b32 t|p, %16, 256, %16, 0xc0, q;\n\t"
        "@p add.rn.f32x2 %8, %8, %17;\n\t"
        "lop3.or.b32 t|p, %16, 512, %16, 0xc0, q;\n\t"
        "@p add.rn.f32x2 %9, %9, %17;\n\t"
        "lop3.or.b32 t|p, %16, 1024, %16, 0xc0, q;\n\t"
        "@p add.rn.f32x2 %10, %10, %17;\n\t"
        "lop3.or.b32 t|p, %16, 2048, %16, 0xc0, q;\n\t"
        "@p add.rn.f32x2 %11, %11, %17;\n\t"
        "lop3.or.b32 t|p, %16, 4096, %16, 0xc0, q;\n\t"
        "@p add.rn.f32x2 %12, %12, %17;\n\t"
        "lop3.or.b32 t|p, %16, 8192, %16, 0xc0, q;\n\t"
        "@p add.rn.f32x2 %13, %13, %17;\n\t"
        "lop3.or.b32 t|p, %16, 16384, %16, 0xc0, q;\n\t"
        "@p add.rn.f32x2 %14, %14, %17;\n\t"
        "lop3.or.b32 t|p, %16, 32768, %16, 0xc0, q;\n\t"
        "@p add.rn.f32x2 %15, %15, %17;\n\t"
        "}"
        : "+l"(acc[0]),  "+l"(acc[1]),  "+l"(acc[2]),  "+l"(acc[3]),
          "+l"(acc[4]),  "+l"(acc[5]),  "+l"(acc[6]),  "+l"(acc[7]),
          "+l"(acc[8]),  "+l"(acc[9]),  "+l"(acc[10]), "+l"(acc[11]),
          "+l"(acc[12]), "+l"(acc[13]), "+l"(acc[14]), "+l"(acc[15])
        : "r"(mask), "l"(w));
}

// ---------------------------------------------------------------------------
// W2 transpose: W2T[k][n] = W2[n][k]. 32x32 tiles, run once per launch.
// ---------------------------------------------------------------------------
__global__ __launch_bounds__(256) void k_transpose(
    const float* __restrict__ W2, float* __restrict__ W2T)
{
    __shared__ float t[32][33];
    const int bk = blockIdx.x * 32;   // k block
    const int bn = blockIdx.y * 32;   // n block
#pragma unroll
    for (int j = threadIdx.y; j < 32; j += 8)
        t[j][threadIdx.x] = W2[(size_t)(bn + j) * H_DIM + bk + threadIdx.x];
    __syncthreads();
#pragma unroll
    for (int j = threadIdx.y; j < 32; j += 8)
        W2T[(size_t)(bk + j) * H_DIM + bn + threadIdx.x] = t[threadIdx.x][j];
}

// ---------------------------------------------------------------------------
// NT SGEMM for cur1 — BIT-EXACT chain (m1=0 proven rounds 3-14). Unchanged.
// ---------------------------------------------------------------------------
__global__ __launch_bounds__(256) void sgemm_nt(
    const float* __restrict__ A, const float* __restrict__ B,
    const float* __restrict__ bias, float* __restrict__ C,
    int M, int N, int K)
{
    __shared__ float As[8][128];
    __shared__ float Bs[8][128];

    const int tid = threadIdx.x;
    const int bm = blockIdx.y * 128;
    const int bn = blockIdx.x * 128;

    const int lrow = tid >> 1;
    const int lcol = (tid & 1) * 4;

    const int tx = tid & 15;
    const int ty = tid >> 4;

    unsigned long long acc[8][4];
#pragma unroll
    for (int i = 0; i < 8; i++)
#pragma unroll
        for (int j = 0; j < 4; j++) acc[i][j] = 0ULL;

    const float* Aptr = A + (size_t)(bm + lrow) * K + lcol;
    const float* Bptr = B + (size_t)(bn + lrow) * K + lcol;

    for (int k0 = 0; k0 < K; k0 += 8) {
        float4 a4 = *(const float4*)(Aptr + k0);
        float4 b4 = *(const float4*)(Bptr + k0);
        As[lcol + 0][lrow] = a4.x; As[lcol + 1][lrow] = a4.y;
        As[lcol + 2][lrow] = a4.z; As[lcol + 3][lrow] = a4.w;
        Bs[lcol + 0][lrow] = b4.x; Bs[lcol + 1][lrow] = b4.y;
        Bs[lcol + 2][lrow] = b4.z; Bs[lcol + 3][lrow] = b4.w;
        __syncthreads();

#pragma unroll
        for (int k = 0; k < 8; k++) {
            float ar[8];
            float4 t;
            t = *(const float4*)&As[k][ty * 8];     ar[0]=t.x; ar[1]=t.y; ar[2]=t.z; ar[3]=t.w;
            t = *(const float4*)&As[k][ty * 8 + 4]; ar[4]=t.x; ar[5]=t.y; ar[6]=t.z; ar[7]=t.w;
            float4 b0 = *(const float4*)&Bs[k][tx * 8];
            float4 b1 = *(const float4*)&Bs[k][tx * 8 + 4];
            unsigned long long bp[4];
            bp[0] = pack2(b0.x, b0.y); bp[1] = pack2(b0.z, b0.w);
            bp[2] = pack2(b1.x, b1.y); bp[3] = pack2(b1.z, b1.w);
#pragma unroll
            for (int i = 0; i < 8; i++) {
                unsigned long long ap = pack2(ar[i], ar[i]);
#pragma unroll
                for (int j = 0; j < 4; j++)
                    fma2(acc[i][j], ap, bp[j]);
            }
        }
        __syncthreads();
    }

    const int row0 = bm + ty * 8;
    const int col0 = bn + tx * 8;
#pragma unroll
    for (int i = 0; i < 8; i++) {
#pragma unroll
        for (int jv = 0; jv < 2; jv++) {
            float2 p0 = unpack2(acc[i][jv * 2 + 0]);
            float2 p1 = unpack2(acc[i][jv * 2 + 1]);
            float4 v;
            v.x = __fadd_rn(p0.x, bias[col0 + jv * 4 + 0]);
            v.y = __fadd_rn(p0.y, bias[col0 + jv * 4 + 1]);
            v.z = __fadd_rn(p1.x, bias[col0 + jv * 4 + 2]);
            v.w = __fadd_rn(p1.y, bias[col0 + jv * 4 + 3]);
            *(float4*)(C + (size_t)(row0 + i) * N + col0 + jv * 4) = v;
        }
    }
}

// ---------------------------------------------------------------------------
// m1 scan (BIT-EXACT chain) — emits spike bits via ballot. Unchanged.
// ---------------------------------------------------------------------------
__global__ void k_scan1(const float* __restrict__ cur1,
                        const float* __restrict__ mem1,
                        const float* __restrict__ beta1p,
                        float* __restrict__ m1_out,
                        unsigned* __restrict__ S1bits)
{
    size_t e = (size_t)blockIdx.x * blockDim.x + threadIdx.x;
    if (e >= NELEM) return;
    const int lane = threadIdx.x & 31;
    const size_t row = e / H_DIM;
    const size_t wcol = (e % H_DIM) >> 5;
    const float beta = *beta1p;
    const float c = cur1[e];
    float m = mem1[e];
#pragma unroll
    for (int k = 0; k < T_STEPS; k++) {
        float reset = (m > 1.0f) ? 1.0f : 0.0f;
        m = __fsub_rn(fmaf(beta, m, c), reset);
        unsigned w = __ballot_sync(0xFFFFFFFFu, m > 1.0f);
        if (lane == 0)
            S1bits[((size_t)k * MROWS + row) * KWORDS + wcol] = w;
    }
    m1_out[e] = m;
}

// ---------------------------------------------------------------------------
// Index prepass (r12 version, stride updated): per (tb, slice) union spike
// list over 16 steps, ascending k, u64 {lo32 = k_local*SMSTR*4, hi32 = step
// mask}; padded to even count + 8 prefetch pads with {ZOFF, 0}.
// ---------------------------------------------------------------------------
__global__ __launch_bounds__(256) void k_index(
    const unsigned* __restrict__ S1bits,
    unsigned long long* __restrict__ ent, unsigned* __restrict__ cnt)
{
    const int task = (blockIdx.x * blockDim.x + threadIdx.x) >> 5;
    const int lane = threadIdx.x & 31;
    if (task >= MROWS * 4) return;
    const int tb = task >> 2;
    const int s  = task & 3;

    unsigned w16[T_STEPS];
    unsigned uni = 0;
#pragma unroll
    for (int st = 0; st < T_STEPS; st++) {
        unsigned w = 0;
        if (lane < 16)
            w = S1bits[((size_t)st * MROWS + tb) * KWORDS + s * 16 + lane];
        w16[st] = w;
        uni |= w;
    }
    int c = __popc(uni);

    int incl = c;
#pragma unroll
    for (int o = 1; o < 32; o <<= 1) {
        int v = __shfl_up_sync(0xFFFFFFFFu, incl, o);
        if (lane >= o) incl += v;
    }
    int excl = incl - c;
    int total = __shfl_sync(0xFFFFFFFFu, incl, 31);
    int tot2 = (total + 1) & ~1;

    unsigned long long* base = ent + (size_t)task * ENTCAP;
    int pos = excl;
    unsigned u = uni;
    while (u) {
        int b = __ffs(u) - 1;
        u &= u - 1;
        unsigned mask = 0;
#pragma unroll
        for (int st = 0; st < T_STEPS; st++)
            mask |= ((w16[st] >> b) & 1u) << st;
        unsigned off = (unsigned)(lane * 32 + b) * (SMSTR * 4);
        base[pos++] = ((unsigned long long)mask << 32) | off;
    }
    if (lane == 0) {
        int pend = total + 8;
        if (pend > ENTCAP) pend = ENTCAP;
        for (int p = total; p < pend; p++)
            base[p] = (unsigned long long)ZOFF;   // mask=0 pad
        cnt[task] = (unsigned)tot2;
    }
}

// ---------------------------------------------------------------------------
// SPARSE big GEMM v7 (r12 skeleton): union lists, 16 step-accs per warp,
// single-alu LOP3.pred bit test, W2T-sourced vectorized tile load (no
// transpose scatter). Ascending k -> PROVEN sliced1x4 chain per step.
// Grid (32 nblk, 8 tb-groups, 4 slices), 768 threads (24 warps).
// ---------------------------------------------------------------------------
__global__ __launch_bounds__(768) void sgemm_sparse(
    const float* __restrict__ W2T,
    const unsigned long long* __restrict__ ent, const unsigned* __restrict__ cnt,
    float* __restrict__ P)
{
    extern __shared__ float sm[];        // [513][SMSTR]
    const int tid  = threadIdx.x;
    const int lane = tid & 31;
    const int warp = tid >> 5;
    const int n0    = blockIdx.x * 64;
    const int tbb   = blockIdx.y * 128;
    const int s     = blockIdx.z;
    const int ks    = s * 512;

    // Vectorized tile load from W2T: sm[k*SMSTR + r] = W2T[ks+k][n0+r]
    // (coalesced LDG.128 -> STS.128, no transpose)
    for (int i = tid; i < 512 * 16; i += 768) {
        int k = i >> 4;
        int q = (i & 15) * 4;
        float4 v = *(const float4*)(W2T + (size_t)(ks + k) * H_DIM + n0 + q);
        *(float4*)(sm + k * SMSTR + q) = v;
    }
    if (tid < SMSTR) sm[512 * SMSTR + tid] = 0.0f;   // zero pad row
    __syncthreads();

    const char* smB = (const char*)sm + 8 * lane;   // lane's n-pair column
    float* Pbase = P + (size_t)s * PSTRIDE + n0 + 2 * lane;

    for (int i = warp; i < 128; i += 24) {
        const int tb = tbb + i;
        const int task = tb * 4 + s;
        const int nvec = ((int)cnt[task]) >> 1;     // uint4s (2 entries each)
        const uint4* lp = (const uint4*)(ent + (size_t)task * ENTCAP);

        unsigned long long acc[T_STEPS];
#pragma unroll
        for (int st = 0; st < T_STEPS; st++) acc[st] = 0ULL;

        // 4-deep prefetch pipeline (pads guarantee initialized reads)
        uint4 q0 = lp[0], q1 = lp[1], q2 = lp[2], q3 = lp[3];
        unsigned long long w0 = *(const unsigned long long*)(smB + q0.x);
        unsigned long long w1 = *(const unsigned long long*)(smB + q0.z);

#pragma unroll 4
        for (int j = 0; j < nvec; j++) {
            uint4 qn = lp[j + 4];
            unsigned long long nw0 = *(const unsigned long long*)(smB + q1.x);
            unsigned long long nw1 = *(const unsigned long long*)(smB + q1.z);
            entry_adds(acc, q0.y, w0);
            entry_adds(acc, q0.w, w1);
            q0 = q1; q1 = q2; q2 = q3; q3 = qn;
            w0 = nw0; w1 = nw1;
        }

#pragma unroll
        for (int st = 0; st < T_STEPS; st++) {
            float2 r = unpack2(acc[st]);
            *(float2*)(Pbase + ((size_t)st * MROWS + tb) * H_DIM) = r;
        }
    }
}

// ---------------------------------------------------------------------------
// m2 scan with fused slice merge: h = (((P0+P1)+P2)+P3) + b2, then the
// proven FMA-form leaky chain. Unchanged (measured correct rounds 9-14).
// ---------------------------------------------------------------------------
__global__ void k_scan2(const float* __restrict__ P,
                        const float* __restrict__ b2,
                        const float* __restrict__ mem2,
                        const float* __restrict__ beta2p,
                        float* __restrict__ m2_out,
                        float* __restrict__ S2)
{
    size_t e = (size_t)blockIdx.x * blockDim.x + threadIdx.x;
    if (e >= NELEM) return;
    const float beta = *beta2p;
    const float bias = b2[e & (H_DIM - 1)];
    float m = mem2[e];
#pragma unroll
    for (int k = 0; k < T_STEPS; k++) {
        size_t o = (size_t)k * NELEM + e;
        float h = __fadd_rn(P[o], P[PSTRIDE + o]);
        h = __fadd_rn(h, P[2 * PSTRIDE + o]);
        h = __fadd_rn(h, P[3 * PSTRIDE + o]);
        h = __fadd_rn(h, bias);
        float reset = (m > 1.0f) ? 1.0f : 0.0f;
        m = __fsub_rn(fmaf(beta, m, h), reset);
    }
    m2_out[e] = m;
    S2[e] = (m > 1.0f) ? 1.0f : 0.0f;
}

// ---------------------------------------------------------------------------
// Heads: value/action + leaky epilogues (FMA form). One block per row.
// ---------------------------------------------------------------------------
__global__ __launch_bounds__(256) void k_heads(
    const float* __restrict__ S2,
    const float* __restrict__ Wc, const float* __restrict__ bc,
    const float* __restrict__ Wa, const float* __restrict__ ba,
    const float* __restrict__ mem_act, const float* __restrict__ mem_crit,
    const float* __restrict__ beta_critp, const float* __restrict__ beta_actp,
    float* __restrict__ out)
{
    const int i = blockIdx.x;
    __shared__ float row[H_DIM];
    for (int h = threadIdx.x; h < H_DIM; h += blockDim.x)
        row[h] = S2[(size_t)i * H_DIM + h];
    __syncthreads();

    float acc[33];
#pragma unroll
    for (int a = 0; a < 33; a++) acc[a] = 0.0f;

    for (int h = threadIdx.x; h < H_DIM; h += blockDim.x) {
        float s = row[h];
        if (s != 0.0f) {
            acc[0] += Wc[h];
#pragma unroll
            for (int a = 0; a < 32; a++)
                acc[a + 1] += Wa[(size_t)a * H_DIM + h];
        }
    }

#pragma unroll
    for (int a = 0; a < 33; a++)
#pragma unroll
        for (int off = 16; off > 0; off >>= 1)
            acc[a] += __shfl_xor_sync(0xFFFFFFFFu, acc[a], off);

    __shared__ float part[8][33];
    const int wid = threadIdx.x >> 5, lane = threadIdx.x & 31;
    if (lane == 0) {
#pragma unroll
        for (int a = 0; a < 33; a++) part[wid][a] = acc[a];
    }
    __syncthreads();

    if (threadIdx.x < 33) {
        const int a = threadIdx.x;
        float y = 0.0f;
#pragma unroll
        for (int w = 0; w < 8; w++) y += part[w][a];
        if (a == 0) {
            y = __fadd_rn(y, bc[0]);
            const float beta = *beta_critp;
            float mem = mem_crit[i];
            float reset = (mem > 1.0f) ? 1.0f : 0.0f;
            float m = __fsub_rn(fmaf(beta, mem, y), reset);
            out[OFF_VALUE + i] = (m > 1.0f) ? 1.0f : 0.0f;
            out[OFF_MCRIT + i] = m;
        } else {
            const int j = a - 1;
            y = __fadd_rn(y, ba[j]);
            const float beta = *beta_actp;
            float mem = mem_act[(size_t)i * A_DIM + j];
            float reset = (mem > 1.0f) ? 1.0f : 0.0f;
            float m = __fsub_rn(fmaf(beta, mem, y), reset);
            out[OFF_ACTION + (size_t)i * A_DIM + j] = (m > 1.0f) ? 1.0f : 0.0f;
            out[OFF_MACT + (size_t)i * A_DIM + j] = m;
        }
    }
}

// ---------------------------------------------------------------------------
extern "C" void kernel_launch(void* const* d_in, const int* in_sizes, int n_in,
                              void* d_out, int out_size)
{
    const float* inputs   = (const float*)d_in[0];
    const float* mem1     = (const float*)d_in[1];
    const float* mem2     = (const float*)d_in[2];
    const float* mem_act  = (const float*)d_in[3];
    const float* mem_crit = (const float*)d_in[4];
    const float* W1 = (const float*)d_in[5];
    const float* b1 = (const float*)d_in[6];
    const float* W2 = (const float*)d_in[7];
    const float* b2 = (const float*)d_in[8];
    const float* Wc = (const float*)d_in[9];
    const float* bc = (const float*)d_in[10];
    const float* Wa = (const float*)d_in[11];
    const float* ba = (const float*)d_in[12];
    const float* beta1     = (const float*)d_in[13];
    const float* beta2     = (const float*)d_in[14];
    const float* beta_crit = (const float*)d_in[15];
    const float* beta_act  = (const float*)d_in[16];
    float* out = (float*)d_out;

    float *cur1, *W2T, *Pp, *S2;
    unsigned *S1bits, *cnt;
    unsigned long long* ent;
    cudaGetSymbolAddress((void**)&cur1, g_cur1);
    cudaGetSymbolAddress((void**)&W2T, g_W2T);
    cudaGetSymbolAddress((void**)&S1bits, g_S1bits);
    cudaGetSymbolAddress((void**)&ent, g_ent);
    cudaGetSymbolAddress((void**)&cnt, g_cnt);
    cudaGetSymbolAddress((void**)&Pp, g_P);
    cudaGetSymbolAddress((void**)&S2, g_S2);

    static const int SMEM_BYTES = 513 * SMSTR * 4;  // 139536
    cudaFuncSetAttribute(sgemm_sparse,
                         cudaFuncAttributeMaxDynamicSharedMemorySize,
                         SMEM_BYTES);

    // 0) W2 transpose (once per launch; overlaps nothing critical)
    k_transpose<<<dim3(H_DIM / 32, H_DIM / 32), dim3(32, 8)>>>(W2, W2T);

    // 1) cur1 = inputs @ W1^T + b1 (bit-exact chain)
    sgemm_nt<<<dim3(H_DIM / 128, MROWS / 128), 256>>>(
        inputs, W1, b1, cur1, MROWS, H_DIM, S_DIM);

    // 2) m1 scan -> spike bits + m1 final
    k_scan1<<<(unsigned)((NELEM + 255) / 256), 256>>>(
        cur1, mem1, beta1, out + OFF_M1, S1bits);

    // 3) index prepass: union lists with step masks (+8 pads)
    k_index<<<(MROWS * 4) / 8, 256>>>(S1bits, ent, cnt);

    // 4) sparse big GEMM v7: LOP3.pred bit test + vectorized tile load
    sgemm_sparse<<<dim3(H_DIM / 64, MROWS / 128, 4), 768, SMEM_BYTES>>>(
        W2T, ent, cnt, Pp);

    // 5) m2 scan with fused slice merge + bias -> m2 final, S2 spikes
    k_scan2<<<(unsigned)((NELEM + 255) / 256), 256>>>(
        Pp, b2, mem2, beta2, out + OFF_M2, S2);

    // 6) heads
    k_heads<<<MROWS, 256>>>(S2, Wc, bc, Wa, ba, mem_act, mem_crit,
                            beta_crit, beta_act, out);
}

// round 16
// speedup vs baseline: 1.2727x; 1.2727x over previous
#include <cuda_runtime.h>
#include <cstddef>

// Problem dims
#define T_STEPS 16
#define B_DIM   64
#define S_DIM   512
#define H_DIM   2048
#define A_DIM   32
#define MROWS   (T_STEPS * B_DIM)          // 1024 (tb rows)
#define NELEM   ((size_t)MROWS * H_DIM)    // 2,097,152
#define MBIG    (T_STEPS * MROWS)          // 16384
#define KWORDS  (H_DIM / 32)               // 64 bit-words per S1 row
#define PSTRIDE ((size_t)MBIG * H_DIM)     // one slice-partial plane
#define ENTCAP  520                        // per-(tb,slice) entries (u64)
#define TSTR    132                        // 128 + 4 pad floats per k-row (16B-aligned)
#define ZOFF    (256u * TSTR * 4u)         // byte offset of the zero pad row

// Output layout: concat of (value, action, m1, m2, m_act, m_crit), fp32
#define OFF_VALUE  0
#define OFF_ACTION 1024
#define OFF_M1     33792
#define OFF_M2     2130944
#define OFF_MACT   4228096
#define OFF_MCRIT  4260864

// Scratch (device globals: allocation-free per harness rules)
__device__ float    g_cur1[MROWS * H_DIM];                  // 8 MB
__device__ float    g_W2T[(size_t)H_DIM * H_DIM];           // 16 MB: W2T[k][n]
__device__ unsigned g_S1bits[(size_t)MBIG * KWORDS];        // 4 MB spike bits
__device__ unsigned long long g_ent[(size_t)MROWS * 4 * ENTCAP]; // 17 MB
__device__ unsigned g_cnt[MROWS * 4];                       // chunk counts packed
__device__ float    g_P[(size_t)4 * MBIG * H_DIM];          // 512 MB slice partials
__device__ float    g_S2[MROWS * H_DIM];                    // 8 MB

// ---------------------------------------------------------------------------
// Packed f32x2 helpers
// ---------------------------------------------------------------------------
__device__ __forceinline__ unsigned long long pack2(float x, float y) {
    unsigned long long r;
    asm("mov.b64 %0, {%1, %2};" : "=l"(r) : "f"(x), "f"(y));
    return r;
}
__device__ __forceinline__ void fma2(unsigned long long& acc,
                                     unsigned long long a,
                                     unsigned long long b) {
    asm("fma.rn.f32x2 %0, %1, %2, %0;" : "+l"(acc) : "l"(a), "l"(b));
}
__device__ __forceinline__ float2 unpack2(unsigned long long v) {
    float2 f;
    asm("mov.b64 {%0, %1}, %2;" : "=f"(f.x), "=f"(f.y) : "l"(v));
    return f;
}
// ONE bit test (immediate mask) guards TWO packed adds (128 n per warp).
// Skip / +0.0-pad adds are bit-neutral (acc never -0) — proven rounds 8-15.
template <int BIT>
__device__ __forceinline__ void bitadd2x2_imm(unsigned long long& a0,
                                              unsigned long long& a1,
                                              unsigned mask,
                                              unsigned long long wA,
                                              unsigned long long wB) {
    asm("{\n\t"
        ".reg .pred p;\n\t"
        ".reg .b32 t;\n\t"
        "and.b32 t, %2, %3;\n\t"
        "setp.ne.b32 p, t, 0;\n\t"
        "@p add.rn.f32x2 %0, %0, %4;\n\t"
        "@p add.rn.f32x2 %1, %1, %5;\n\t"
        "}"
        : "+l"(a0), "+l"(a1)
        : "r"(mask), "n"(1 << BIT), "l"(wA), "l"(wB));
}

#define BITADD_ALL(M, WA, WB)                                   \
    do {                                                        \
        bitadd2x2_imm<0>(accA[0],  accB[0],  (M), (WA), (WB));  \
        bitadd2x2_imm<1>(accA[1],  accB[1],  (M), (WA), (WB));  \
        bitadd2x2_imm<2>(accA[2],  accB[2],  (M), (WA), (WB));  \
        bitadd2x2_imm<3>(accA[3],  accB[3],  (M), (WA), (WB));  \
        bitadd2x2_imm<4>(accA[4],  accB[4],  (M), (WA), (WB));  \
        bitadd2x2_imm<5>(accA[5],  accB[5],  (M), (WA), (WB));  \
        bitadd2x2_imm<6>(accA[6],  accB[6],  (M), (WA), (WB));  \
        bitadd2x2_imm<7>(accA[7],  accB[7],  (M), (WA), (WB));  \
        bitadd2x2_imm<8>(accA[8],  accB[8],  (M), (WA), (WB));  \
        bitadd2x2_imm<9>(accA[9],  accB[9],  (M), (WA), (WB));  \
        bitadd2x2_imm<10>(accA[10], accB[10], (M), (WA), (WB)); \
        bitadd2x2_imm<11>(accA[11], accB[11], (M), (WA), (WB)); \
        bitadd2x2_imm<12>(accA[12], accB[12], (M), (WA), (WB)); \
        bitadd2x2_imm<13>(accA[13], accB[13], (M), (WA), (WB)); \
        bitadd2x2_imm<14>(accA[14], accB[14], (M), (WA), (WB)); \
        bitadd2x2_imm<15>(accA[15], accB[15], (M), (WA), (WB)); \
    } while (0)

// ---------------------------------------------------------------------------
// W2 transpose: W2T[k][n] = W2[n][k]. 32x32 tiles, once per launch (~5 us).
// ---------------------------------------------------------------------------
__global__ __launch_bounds__(256) void k_transpose(
    const float* __restrict__ W2, float* __restrict__ W2T)
{
    __shared__ float t[32][33];
    const int bk = blockIdx.x * 32;
    const int bn = blockIdx.y * 32;
#pragma unroll
    for (int j = threadIdx.y; j < 32; j += 8)
        t[j][threadIdx.x] = W2[(size_t)(bn + j) * H_DIM + bk + threadIdx.x];
    __syncthreads();
#pragma unroll
    for (int j = threadIdx.y; j < 32; j += 8)
        W2T[(size_t)(bk + j) * H_DIM + bn + threadIdx.x] = t[threadIdx.x][j];
}

// ---------------------------------------------------------------------------
// NT SGEMM for cur1 — BIT-EXACT chain (m1=0 proven rounds 3-15). Unchanged.
// ---------------------------------------------------------------------------
__global__ __launch_bounds__(256) void sgemm_nt(
    const float* __restrict__ A, const float* __restrict__ B,
    const float* __restrict__ bias, float* __restrict__ C,
    int M, int N, int K)
{
    __shared__ float As[8][128];
    __shared__ float Bs[8][128];

    const int tid = threadIdx.x;
    const int bm = blockIdx.y * 128;
    const int bn = blockIdx.x * 128;

    const int lrow = tid >> 1;
    const int lcol = (tid & 1) * 4;

    const int tx = tid & 15;
    const int ty = tid >> 4;

    unsigned long long acc[8][4];
#pragma unroll
    for (int i = 0; i < 8; i++)
#pragma unroll
        for (int j = 0; j < 4; j++) acc[i][j] = 0ULL;

    const float* Aptr = A + (size_t)(bm + lrow) * K + lcol;
    const float* Bptr = B + (size_t)(bn + lrow) * K + lcol;

    for (int k0 = 0; k0 < K; k0 += 8) {
        float4 a4 = *(const float4*)(Aptr + k0);
        float4 b4 = *(const float4*)(Bptr + k0);
        As[lcol + 0][lrow] = a4.x; As[lcol + 1][lrow] = a4.y;
        As[lcol + 2][lrow] = a4.z; As[lcol + 3][lrow] = a4.w;
        Bs[lcol + 0][lrow] = b4.x; Bs[lcol + 1][lrow] = b4.y;
        Bs[lcol + 2][lrow] = b4.z; Bs[lcol + 3][lrow] = b4.w;
        __syncthreads();

#pragma unroll
        for (int k = 0; k < 8; k++) {
            float ar[8];
            float4 t;
            t = *(const float4*)&As[k][ty * 8];     ar[0]=t.x; ar[1]=t.y; ar[2]=t.z; ar[3]=t.w;
            t = *(const float4*)&As[k][ty * 8 + 4]; ar[4]=t.x; ar[5]=t.y; ar[6]=t.z; ar[7]=t.w;
            float4 b0 = *(const float4*)&Bs[k][tx * 8];
            float4 b1 = *(const float4*)&Bs[k][tx * 8 + 4];
            unsigned long long bp[4];
            bp[0] = pack2(b0.x, b0.y); bp[1] = pack2(b0.z, b0.w);
            bp[2] = pack2(b1.x, b1.y); bp[3] = pack2(b1.z, b1.w);
#pragma unroll
            for (int i = 0; i < 8; i++) {
                unsigned long long ap = pack2(ar[i], ar[i]);
#pragma unroll
                for (int j = 0; j < 4; j++)
                    fma2(acc[i][j], ap, bp[j]);
            }
        }
        __syncthreads();
    }

    const int row0 = bm + ty * 8;
    const int col0 = bn + tx * 8;
#pragma unroll
    for (int i = 0; i < 8; i++) {
#pragma unroll
        for (int jv = 0; jv < 2; jv++) {
            float2 p0 = unpack2(acc[i][jv * 2 + 0]);
            float2 p1 = unpack2(acc[i][jv * 2 + 1]);
            float4 v;
            v.x = __fadd_rn(p0.x, bias[col0 + jv * 4 + 0]);
            v.y = __fadd_rn(p0.y, bias[col0 + jv * 4 + 1]);
            v.z = __fadd_rn(p1.x, bias[col0 + jv * 4 + 2]);
            v.w = __fadd_rn(p1.y, bias[col0 + jv * 4 + 3]);
            *(float4*)(C + (size_t)(row0 + i) * N + col0 + jv * 4) = v;
        }
    }
}

// ---------------------------------------------------------------------------
// m1 scan (BIT-EXACT chain) — emits spike bits via ballot. Unchanged.
// ---------------------------------------------------------------------------
__global__ void k_scan1(const float* __restrict__ cur1,
                        const float* __restrict__ mem1,
                        const float* __restrict__ beta1p,
                        float* __restrict__ m1_out,
                        unsigned* __restrict__ S1bits)
{
    size_t e = (size_t)blockIdx.x * blockDim.x + threadIdx.x;
    if (e >= NELEM) return;
    const int lane = threadIdx.x & 31;
    const size_t row = e / H_DIM;
    const size_t wcol = (e % H_DIM) >> 5;
    const float beta = *beta1p;
    const float c = cur1[e];
    float m = mem1[e];
#pragma unroll
    for (int k = 0; k < T_STEPS; k++) {
        float reset = (m > 1.0f) ? 1.0f : 0.0f;
        m = __fsub_rn(fmaf(beta, m, c), reset);
        unsigned w = __ballot_sync(0xFFFFFFFFu, m > 1.0f);
        if (lane == 0)
            S1bits[((size_t)k * MROWS + row) * KWORDS + wcol] = w;
    }
    m1_out[e] = m;
}

// ---------------------------------------------------------------------------
// Index prepass (chunked, r13-proven): per (tb, slice) union lists split into
// TWO 256-k chunks (ascending k, chunk-relative byte offsets
// (k&255)*TSTR*4, 16-bit step masks in hi32). Each chunk padded to even
// count with {ZOFF,0}; +8 pads at the end. cnt = c0p | (c1p << 16).
// ---------------------------------------------------------------------------
__global__ __launch_bounds__(256) void k_index(
    const unsigned* __restrict__ S1bits,
    unsigned long long* __restrict__ ent, unsigned* __restrict__ cnt)
{
    const int task = (blockIdx.x * blockDim.x + threadIdx.x) >> 5;
    const int lane = threadIdx.x & 31;
    if (task >= MROWS * 4) return;
    const int tb = task >> 2;
    const int s  = task & 3;

    unsigned w16[T_STEPS];
    unsigned uni = 0;
#pragma unroll
    for (int st = 0; st < T_STEPS; st++) {
        unsigned w = 0;
        if (lane < 16)
            w = S1bits[((size_t)st * MROWS + tb) * KWORDS + s * 16 + lane];
        w16[st] = w;
        uni |= w;
    }
    int c = __popc(uni);

    int incl = c;
#pragma unroll
    for (int o = 1; o < 32; o <<= 1) {
        int v = __shfl_up_sync(0xFFFFFFFFu, incl, o);
        if (lane >= o) incl += v;
    }
    int excl = incl - c;
    int c0_total = __shfl_sync(0xFFFFFFFFu, incl, 7);
    int total    = __shfl_sync(0xFFFFFFFFu, incl, 31);
    int c1 = total - c0_total;
    int c0p = (c0_total + 1) & ~1;
    int c1p = (c1 + 1) & ~1;

    unsigned long long* base = ent + (size_t)task * ENTCAP;
    int pos = (lane < 8) ? excl : (c0p + (excl - c0_total));
    unsigned u = uni;
    while (u) {
        int b = __ffs(u) - 1;
        u &= u - 1;
        unsigned mask = 0;
#pragma unroll
        for (int st = 0; st < T_STEPS; st++)
            mask |= ((w16[st] >> b) & 1u) << st;
        unsigned off = (unsigned)((lane & 7) * 32 + b) * (TSTR * 4);
        base[pos++] = ((unsigned long long)mask << 32) | off;
    }
    if (lane == 0) {
        for (int p = c0_total; p < c0p; p++)
            base[p] = (unsigned long long)ZOFF;              // chunk0 pad
        int pend = c0p + c1p + 8;
        if (pend > ENTCAP) pend = ENTCAP;
        for (int p = c0p + c1; p < pend; p++)
            base[p] = (unsigned long long)ZOFF;              // chunk1 + prefetch pads
        cnt[task] = (unsigned)(c0p | (c1p << 16));
    }
}

// ---------------------------------------------------------------------------
// SPARSE big GEMM v8: 128 n per warp (halved list replication), W2T-sourced
// vectorized tile load (no transpose scatter, conflict-free STS.128),
// immediate-mask bit tests, 2-deep prefetch. Slice = two 256-k chunks with
// accs persisting across the reload -> ascending-k per slice = PROVEN
// sliced1x4 chain per step. One warp per (tb, slice, 128n).
// Grid (16 nblk, 64 tb-groups, 4 slices), 512 threads, ~136 KB smem.
// ---------------------------------------------------------------------------
__global__ __launch_bounds__(512) void sgemm_sparse(
    const float* __restrict__ W2T,
    const unsigned long long* __restrict__ ent, const unsigned* __restrict__ cnt,
    float* __restrict__ P)
{
    extern __shared__ float sm[];        // [257][TSTR]
    const int tid  = threadIdx.x;
    const int lane = tid & 31;
    const int warp = tid >> 5;
    const int n0 = blockIdx.x * 128;
    const int tb = blockIdx.y * 16 + warp;
    const int s  = blockIdx.z;

    const int task = tb * 4 + s;
    const unsigned cw = cnt[task];
    const int c0p = (int)(cw & 0xFFFFu);
    const int c1p = (int)(cw >> 16);
    const unsigned long long* list = ent + (size_t)task * ENTCAP;

    unsigned long long accA[T_STEPS], accB[T_STEPS];
#pragma unroll
    for (int st = 0; st < T_STEPS; st++) { accA[st] = 0ULL; accB[st] = 0ULL; }

    const char* smA = (const char*)sm + 8 * lane;          // n-pair A column
    const char* smB = smA + 64 * 4;                        // n-pair B column

#pragma unroll 1
    for (int chunk = 0; chunk < 2; chunk++) {
        __syncthreads();
        // Vectorized tile load from W2T: sm[k*TSTR + n] = W2T[kbase+k][n0+n]
        {
            const float* Wb = W2T + (size_t)(s * 512 + chunk * 256) * H_DIM + n0;
            for (int i = tid; i < 256 * 32; i += 512) {
                int k = i >> 5;
                int q = (i & 31) * 4;
                float4 v = *(const float4*)(Wb + (size_t)k * H_DIM + q);
                *(float4*)(sm + k * TSTR + q) = v;
            }
            if (tid < TSTR) sm[256 * TSTR + tid] = 0.0f;   // zero pad row
        }
        __syncthreads();

        const int nv = (chunk ? c1p : c0p) >> 1;           // uint4 count
        const uint4* lp = (const uint4*)(list + (chunk ? c0p : 0));

        // 2-deep uint4 prefetch; pads guarantee initialized reads
        uint4 q0 = lp[0], q1 = lp[1];
        unsigned long long wA0 = *(const unsigned long long*)(smA + q0.x);
        unsigned long long wB0 = *(const unsigned long long*)(smB + q0.x);
        unsigned long long wA1 = *(const unsigned long long*)(smA + q0.z);
        unsigned long long wB1 = *(const unsigned long long*)(smB + q0.z);

#pragma unroll 2
        for (int j = 0; j < nv; j++) {
            uint4 qn = lp[j + 2];
            unsigned long long nA0 = *(const unsigned long long*)(smA + q1.x);
            unsigned long long nB0 = *(const unsigned long long*)(smB + q1.x);
            unsigned long long nA1 = *(const unsigned long long*)(smA + q1.z);
            unsigned long long nB1 = *(const unsigned long long*)(smB + q1.z);
            const unsigned m0 = q0.y, m1 = q0.w;
            BITADD_ALL(m0, wA0, wB0);
            BITADD_ALL(m1, wA1, wB1);
            q0 = q1; q1 = qn;
            wA0 = nA0; wB0 = nB0; wA1 = nA1; wB1 = nB1;
        }
    }

    float* Pb = P + (size_t)s * PSTRIDE + n0 + 2 * lane;
#pragma unroll
    for (int st = 0; st < T_STEPS; st++) {
        float2 rA = unpack2(accA[st]);
        float2 rB = unpack2(accB[st]);
        float* row = Pb + ((size_t)st * MROWS + tb) * H_DIM;
        *(float2*)row = rA;
        *(float2*)(row + 64) = rB;
    }
}

// ---------------------------------------------------------------------------
// m2 scan with fused slice merge: h = (((P0+P1)+P2)+P3) + b2, then the
// proven FMA-form leaky chain. Unchanged (measured correct rounds 9-15).
// ---------------------------------------------------------------------------
__global__ void k_scan2(const float* __restrict__ P,
                        const float* __restrict__ b2,
                        const float* __restrict__ mem2,
                        const float* __restrict__ beta2p,
                        float* __restrict__ m2_out,
                        float* __restrict__ S2)
{
    size_t e = (size_t)blockIdx.x * blockDim.x + threadIdx.x;
    if (e >= NELEM) return;
    const float beta = *beta2p;
    const float bias = b2[e & (H_DIM - 1)];
    float m = mem2[e];
#pragma unroll
    for (int k = 0; k < T_STEPS; k++) {
        size_t o = (size_t)k * NELEM + e;
        float h = __fadd_rn(P[o], P[PSTRIDE + o]);
        h = __fadd_rn(h, P[2 * PSTRIDE + o]);
        h = __fadd_rn(h, P[3 * PSTRIDE + o]);
        h = __fadd_rn(h, bias);
        float reset = (m > 1.0f) ? 1.0f : 0.0f;
        m = __fsub_rn(fmaf(beta, m, h), reset);
    }
    m2_out[e] = m;
    S2[e] = (m > 1.0f) ? 1.0f : 0.0f;
}

// ---------------------------------------------------------------------------
// Heads: value/action + leaky epilogues (FMA form). One block per row.
// ---------------------------------------------------------------------------
__global__ __launch_bounds__(256) void k_heads(
    const float* __restrict__ S2,
    const float* __restrict__ Wc, const float* __restrict__ bc,
    const float* __restrict__ Wa, const float* __restrict__ ba,
    const float* __restrict__ mem_act, const float* __restrict__ mem_crit,
    const float* __restrict__ beta_critp, const float* __restrict__ beta_actp,
    float* __restrict__ out)
{
    const int i = blockIdx.x;
    __shared__ float row[H_DIM];
    for (int h = threadIdx.x; h < H_DIM; h += blockDim.x)
        row[h] = S2[(size_t)i * H_DIM + h];
    __syncthreads();

    float acc[33];
#pragma unroll
    for (int a = 0; a < 33; a++) acc[a] = 0.0f;

    for (int h = threadIdx.x; h < H_DIM; h += blockDim.x) {
        float s = row[h];
        if (s != 0.0f) {
            acc[0] += Wc[h];
#pragma unroll
            for (int a = 0; a < 32; a++)
                acc[a + 1] += Wa[(size_t)a * H_DIM + h];
        }
    }

#pragma unroll
    for (int a = 0; a < 33; a++)
#pragma unroll
        for (int off = 16; off > 0; off >>= 1)
            acc[a] += __shfl_xor_sync(0xFFFFFFFFu, acc[a], off);

    __shared__ float part[8][33];
    const int wid = threadIdx.x >> 5, lane = threadIdx.x & 31;
    if (lane == 0) {
#pragma unroll
        for (int a = 0; a < 33; a++) part[wid][a] = acc[a];
    }
    __syncthreads();

    if (threadIdx.x < 33) {
        const int a = threadIdx.x;
        float y = 0.0f;
#pragma unroll
        for (int w = 0; w < 8; w++) y += part[w][a];
        if (a == 0) {
            y = __fadd_rn(y, bc[0]);
            const float beta = *beta_critp;
            float mem = mem_crit[i];
            float reset = (mem > 1.0f) ? 1.0f : 0.0f;
            float m = __fsub_rn(fmaf(beta, mem, y), reset);
            out[OFF_VALUE + i] = (m > 1.0f) ? 1.0f : 0.0f;
            out[OFF_MCRIT + i] = m;
        } else {
            const int j = a - 1;
            y = __fadd_rn(y, ba[j]);
            const float beta = *beta_actp;
            float mem = mem_act[(size_t)i * A_DIM + j];
            float reset = (mem > 1.0f) ? 1.0f : 0.0f;
            float m = __fsub_rn(fmaf(beta, mem, y), reset);
            out[OFF_ACTION + (size_t)i * A_DIM + j] = (m > 1.0f) ? 1.0f : 0.0f;
            out[OFF_MACT + (size_t)i * A_DIM + j] = m;
        }
    }
}

// ---------------------------------------------------------------------------
extern "C" void kernel_launch(void* const* d_in, const int* in_sizes, int n_in,
                              void* d_out, int out_size)
{
    const float* inputs   = (const float*)d_in[0];
    const float* mem1     = (const float*)d_in[1];
    const float* mem2     = (const float*)d_in[2];
    const float* mem_act  = (const float*)d_in[3];
    const float* mem_crit = (const float*)d_in[4];
    const float* W1 = (const float*)d_in[5];
    const float* b1 = (const float*)d_in[6];
    const float* W2 = (const float*)d_in[7];
    const float* b2 = (const float*)d_in[8];
    const float* Wc = (const float*)d_in[9];
    const float* bc = (const float*)d_in[10];
    const float* Wa = (const float*)d_in[11];
    const float* ba = (const float*)d_in[12];
    const float* beta1     = (const float*)d_in[13];
    const float* beta2     = (const float*)d_in[14];
    const float* beta_crit = (const float*)d_in[15];
    const float* beta_act  = (const float*)d_in[16];
    float* out = (float*)d_out;

    float *cur1, *W2T, *Pp, *S2;
    unsigned *S1bits, *cnt;
    unsigned long long* ent;
    cudaGetSymbolAddress((void**)&cur1, g_cur1);
    cudaGetSymbolAddress((void**)&W2T, g_W2T);
    cudaGetSymbolAddress((void**)&S1bits, g_S1bits);
    cudaGetSymbolAddress((void**)&ent, g_ent);
    cudaGetSymbolAddress((void**)&cnt, g_cnt);
    cudaGetSymbolAddress((void**)&Pp, g_P);
    cudaGetSymbolAddress((void**)&S2, g_S2);

    static const int SMEM_BYTES = 257 * TSTR * 4;  // 135696
    cudaFuncSetAttribute(sgemm_sparse,
                         cudaFuncAttributeMaxDynamicSharedMemorySize,
                         SMEM_BYTES);

    // 0) W2 transpose (once per launch)
    k_transpose<<<dim3(H_DIM / 32, H_DIM / 32), dim3(32, 8)>>>(W2, W2T);

    // 1) cur1 = inputs @ W1^T + b1 (bit-exact chain)
    sgemm_nt<<<dim3(H_DIM / 128, MROWS / 128), 256>>>(
        inputs, W1, b1, cur1, MROWS, H_DIM, S_DIM);

    // 2) m1 scan -> spike bits + m1 final
    k_scan1<<<(unsigned)((NELEM + 255) / 256), 256>>>(
        cur1, mem1, beta1, out + OFF_M1, S1bits);

    // 3) index prepass: chunked union lists with step masks
    k_index<<<(MROWS * 4) / 8, 256>>>(S1bits, ent, cnt);

    // 4) sparse big GEMM v8: 128n/warp + vectorized W2T tiles
    sgemm_sparse<<<dim3(H_DIM / 128, MROWS / 16, 4), 512, SMEM_BYTES>>>(
        W2T, ent, cnt, Pp);

    // 5) m2 scan with fused slice merge + bias -> m2 final, S2 spikes
    k_scan2<<<(unsigned)((NELEM + 255) / 256), 256>>>(
        Pp, b2, mem2, beta2, out + OFF_M2, S2);

    // 6) heads
    k_heads<<<MROWS, 256>>>(S2, Wc, bc, Wa, ba, mem_act, mem_crit,
                            beta_crit, beta_act, out);
}